// round 8
// baseline (speedup 1.0000x reference)
#include <cuda_runtime.h>
#include <math.h>

// Problem-fixed sizes (registry problem: N=100000 nodes, E=3200000 edges,
// d_in=128, d_hid=64, d_out=4). Runtime sizes are read from in_sizes but the
// static scratch below is dimensioned for these maxima.
#define MAX_N 100000
#define MAX_E 3200000
#define D_IN  128
#define D_HID 64
#define D_OUT 4

// -------- scratch (no cudaMalloc allowed) --------
__device__ float g_dinv[MAX_N];              // deg -> rsqrt(deg), in place
__device__ float g_hs1 [MAX_N * D_HID];      // dinv * (x @ W1)
__device__ float g_agg1[MAX_N * D_HID];      // scatter accumulator, init = hs1
__device__ float g_hs2 [MAX_N * D_OUT];      // dinv * (lrelu(...) @ W2)
__device__ float g_agg2[MAX_N * D_OUT];      // scatter accumulator, init = hs2

// vectorized reduction: 1 op moves 16B through the L2 atomic unit
__device__ __forceinline__ void red_add_v4(float* addr, float4 v) {
    asm volatile("red.global.add.v4.f32 [%0], {%1, %2, %3, %4};"
                 :: "l"(addr), "f"(v.x), "f"(v.y), "f"(v.z), "f"(v.w)
                 : "memory");
}

// ---------------- K0: deg init (self-loop weight = 1) ----------------
__global__ void k_deg_init(int n) {
    int i = blockIdx.x * blockDim.x + threadIdx.x;
    if (i < n) g_dinv[i] = 1.0f;
}

// ---------------- K1: deg accumulate over edges ----------------
__global__ void k_deg_edges(const int* __restrict__ dst,
                            const float* __restrict__ w, int e) {
    int i = blockIdx.x * blockDim.x + threadIdx.x;
    if (i < e) atomicAdd(&g_dinv[dst[i]], w[i]);   // no return -> REDG
}

// ---------------- K2: deg -> rsqrt(deg) ----------------
__global__ void k_rsqrt(int n) {
    int i = blockIdx.x * blockDim.x + threadIdx.x;
    if (i < n) g_dinv[i] = rsqrtf(g_dinv[i]);      // deg >= 1 always
}

// ---------------- K3: hs1 = dinv * (x @ W1); agg1 = hs1 ----------------
// 128 rows/block, 256 threads. Thread computes 2 rows x 16 cols.
// smem: W1 (128x64 = 32KB) + x tile padded to 132 floats/row (67.6KB).
#define G1_ROWS 128
#define G1_PAD  132
__global__ void k_gemm1(const float* __restrict__ x,
                        const float* __restrict__ W1, int n) {
    extern __shared__ float sm[];
    float* Ws = sm;                       // [128*64]
    float* xs = sm + D_IN * D_HID;        // [G1_ROWS * G1_PAD]
    const int tid  = threadIdx.x;
    const int row0 = blockIdx.x * G1_ROWS;

    for (int i = tid; i < D_IN * D_HID; i += 256) Ws[i] = W1[i];
    for (int i = tid; i < G1_ROWS * (D_IN / 4); i += 256) {
        int r  = i >> 5;          // 0..127
        int c4 = i & 31;          // float4 index within row
        float4 v = make_float4(0.f, 0.f, 0.f, 0.f);
        if (row0 + r < n)
            v = reinterpret_cast<const float4*>(x + (size_t)(row0 + r) * D_IN)[c4];
        *reinterpret_cast<float4*>(xs + r * G1_PAD + c4 * 4) = v;
    }
    __syncthreads();

    const int n0 = tid >> 2;              // 0..63  (second row: n0+64)
    const int cg = (tid & 3) * 16;        // column group base
    float acc0[16], acc1[16];
#pragma unroll
    for (int j = 0; j < 16; j++) { acc0[j] = 0.f; acc1[j] = 0.f; }

    for (int k = 0; k < D_IN; k++) {
        float a0 = xs[n0 * G1_PAD + k];
        float a1 = xs[(n0 + 64) * G1_PAD + k];
        const float4* wr = reinterpret_cast<const float4*>(Ws + k * D_HID + cg);
#pragma unroll
        for (int j4 = 0; j4 < 4; j4++) {
            float4 wv = wr[j4];
            acc0[j4 * 4 + 0] += a0 * wv.x;  acc1[j4 * 4 + 0] += a1 * wv.x;
            acc0[j4 * 4 + 1] += a0 * wv.y;  acc1[j4 * 4 + 1] += a1 * wv.y;
            acc0[j4 * 4 + 2] += a0 * wv.z;  acc1[j4 * 4 + 2] += a1 * wv.z;
            acc0[j4 * 4 + 3] += a0 * wv.w;  acc1[j4 * 4 + 3] += a1 * wv.w;
        }
    }

    int r0 = row0 + n0, r1 = row0 + n0 + 64;
    if (r0 < n) {
        float di = g_dinv[r0];
        float* h = g_hs1  + (size_t)r0 * D_HID + cg;
        float* a = g_agg1 + (size_t)r0 * D_HID + cg;
#pragma unroll
        for (int j4 = 0; j4 < 4; j4++) {
            float4 v = make_float4(di * acc0[j4*4+0], di * acc0[j4*4+1],
                                   di * acc0[j4*4+2], di * acc0[j4*4+3]);
            reinterpret_cast<float4*>(h)[j4] = v;
            reinterpret_cast<float4*>(a)[j4] = v;
        }
    }
    if (r1 < n) {
        float di = g_dinv[r1];
        float* h = g_hs1  + (size_t)r1 * D_HID + cg;
        float* a = g_agg1 + (size_t)r1 * D_HID + cg;
#pragma unroll
        for (int j4 = 0; j4 < 4; j4++) {
            float4 v = make_float4(di * acc1[j4*4+0], di * acc1[j4*4+1],
                                   di * acc1[j4*4+2], di * acc1[j4*4+3]);
            reinterpret_cast<float4*>(h)[j4] = v;
            reinterpret_cast<float4*>(a)[j4] = v;
        }
    }
}

// ---------------- K4: layer-1 edge scatter ----------------
// 4 threads per edge; each thread handles 64B (4 x float4) of the 256B row.
__global__ void k_scatter1(const int* __restrict__ src,
                           const int* __restrict__ dst,
                           const float* __restrict__ w, int e) {
    int i = blockIdx.x * blockDim.x + threadIdx.x;
    if (i >= 4 * e) return;
    int ed = i >> 2, q = i & 3;
    int s = src[ed], d = dst[ed];
    float we = w[ed];
    const float4* hr = reinterpret_cast<const float4*>(g_hs1 + (size_t)s * D_HID) + q * 4;
    float* ar = g_agg1 + (size_t)d * D_HID + q * 16;
#pragma unroll
    for (int j = 0; j < 4; j++) {
        float4 v = hr[j];
        red_add_v4(ar + j * 4, make_float4(we * v.x, we * v.y, we * v.z, we * v.w));
    }
}

// ---------------- K5: out1 = lrelu(dinv*agg1 + b1); hs2 = dinv*(out1@W2) ---
// one warp per node; lane l owns cols l and l+32.
__global__ void k_mid(const float* __restrict__ b1,
                      const float* __restrict__ W2, int n) {
    int warp = blockIdx.x * (blockDim.x >> 5) + (threadIdx.x >> 5);
    int lane = threadIdx.x & 31;
    if (warp >= n) return;

    float di = g_dinv[warp];
    const float* row = g_agg1 + (size_t)warp * D_HID;
    float v0 = di * row[lane]      + __ldg(&b1[lane]);
    float v1 = di * row[lane + 32] + __ldg(&b1[lane + 32]);
    v0 = (v0 > 0.f) ? v0 : 0.01f * v0;
    v1 = (v1 > 0.f) ? v1 : 0.01f * v1;

    float4 wa = __ldg(reinterpret_cast<const float4*>(W2) + lane);        // W2[lane][:]
    float4 wb = __ldg(reinterpret_cast<const float4*>(W2) + lane + 32);   // W2[lane+32][:]
    float c0 = v0 * wa.x + v1 * wb.x;
    float c1 = v0 * wa.y + v1 * wb.y;
    float c2 = v0 * wa.z + v1 * wb.z;
    float c3 = v0 * wa.w + v1 * wb.w;
#pragma unroll
    for (int off = 16; off; off >>= 1) {
        c0 += __shfl_xor_sync(0xffffffffu, c0, off);
        c1 += __shfl_xor_sync(0xffffffffu, c1, off);
        c2 += __shfl_xor_sync(0xffffffffu, c2, off);
        c3 += __shfl_xor_sync(0xffffffffu, c3, off);
    }
    if (lane == 0) {
        float4 h2 = make_float4(di * c0, di * c1, di * c2, di * c3);
        reinterpret_cast<float4*>(g_hs2)[warp]  = h2;
        reinterpret_cast<float4*>(g_agg2)[warp] = h2;
    }
}

// ---------------- K6: layer-2 edge scatter (1 thread/edge) ----------------
__global__ void k_scatter2(const int* __restrict__ src,
                           const int* __restrict__ dst,
                           const float* __restrict__ w, int e) {
    int i = blockIdx.x * blockDim.x + threadIdx.x;
    if (i >= e) return;
    int s = src[i], d = dst[i];
    float we = w[i];
    float4 v = reinterpret_cast<const float4*>(g_hs2)[s];
    red_add_v4(g_agg2 + (size_t)d * D_OUT,
               make_float4(we * v.x, we * v.y, we * v.z, we * v.w));
}

// ---------------- K7: out = softmax(dinv*agg2 + b2) ----------------
__global__ void k_softmax(const float* __restrict__ b2,
                          float* __restrict__ out, int n) {
    int i = blockIdx.x * blockDim.x + threadIdx.x;
    if (i >= n) return;
    float di = g_dinv[i];
    float4 a = reinterpret_cast<const float4*>(g_agg2)[i];
    float z0 = di * a.x + __ldg(&b2[0]);
    float z1 = di * a.y + __ldg(&b2[1]);
    float z2 = di * a.z + __ldg(&b2[2]);
    float z3 = di * a.w + __ldg(&b2[3]);
    float m = fmaxf(fmaxf(z0, z1), fmaxf(z2, z3));
    float e0 = __expf(z0 - m), e1 = __expf(z1 - m);
    float e2 = __expf(z2 - m), e3 = __expf(z3 - m);
    float inv = 1.0f / (e0 + e1 + e2 + e3);
    reinterpret_cast<float4*>(out)[i] =
        make_float4(e0 * inv, e1 * inv, e2 * inv, e3 * inv);
}

// ---------------- launch ----------------
extern "C" void kernel_launch(void* const* d_in, const int* in_sizes, int n_in,
                              void* d_out, int out_size) {
    const float* x   = (const float*)d_in[0];   // [N,128]
    const int*   ei  = (const int*)  d_in[1];   // [2,E]
    const float* w   = (const float*)d_in[2];   // [E]
    const float* W1  = (const float*)d_in[3];   // [128,64]
    const float* b1  = (const float*)d_in[4];   // [64]
    const float* W2  = (const float*)d_in[5];   // [64,4]
    const float* b2  = (const float*)d_in[6];   // [4]
    float* out = (float*)d_out;

    const int N = in_sizes[0] / D_IN;
    const int E = in_sizes[2];
    const int* src = ei;
    const int* dst = ei + E;

    static bool attr_set = false;
    const int g1_smem = (D_IN * D_HID + G1_ROWS * G1_PAD) * (int)sizeof(float);
    if (!attr_set) {
        cudaFuncSetAttribute(k_gemm1, cudaFuncAttributeMaxDynamicSharedMemorySize,
                             g1_smem);
        attr_set = true;
    }

    k_deg_init <<<(N + 255) / 256, 256>>>(N);
    k_deg_edges<<<(E + 255) / 256, 256>>>(dst, w, E);
    k_rsqrt    <<<(N + 255) / 256, 256>>>(N);
    k_gemm1    <<<(N + G1_ROWS - 1) / G1_ROWS, 256, g1_smem>>>(x, W1, N);
    k_scatter1 <<<(4 * E + 255) / 256, 256>>>(src, dst, w, E);
    k_mid      <<<(N * 32 + 255) / 256, 256>>>(b1, W2, N);
    k_scatter2 <<<(E + 255) / 256, 256>>>(src, dst, w, E);
    k_softmax  <<<(N + 255) / 256, 256>>>(b2, out, N);
}

// round 9
// speedup vs baseline: 1.6720x; 1.6720x over previous
#include <cuda_runtime.h>
#include <cuda_fp16.h>
#include <math.h>

#define MAX_N 100000
#define MAX_E 3200000
#define D_IN  128
#define D_HID 64
#define D_OUT 4
#define SCAN_B 512
#define MAX_BLK ((MAX_N + SCAN_B - 1) / SCAN_B)

// -------- scratch (no cudaMalloc allowed) --------
__device__ float   g_dinv[MAX_N];
__device__ __half2 g_hs1h[MAX_N * (D_HID / 2)];   // fp16 dinv*(x@W1), 32 half2/node
__device__ float   g_hs2 [MAX_N * D_OUT];         // dinv*(lrelu(...)@W2)
__device__ int     g_cnt [MAX_N];                 // in-degree edge counts
__device__ int     g_rs  [MAX_N];                 // CSR row starts (exclusive scan)
__device__ int     g_cur [MAX_N];                 // fill cursors
__device__ int     g_bsum[MAX_BLK];               // scan block sums
__device__ float2  g_edge[MAX_E];                 // CSR payload: (src as int bits, w)

// ---------------- CSR build ----------------
__global__ void k_zero(int n) {
    int i = blockIdx.x * blockDim.x + threadIdx.x;
    if (i < n) g_cnt[i] = 0;
}

__global__ void k_count(const int* __restrict__ dst, int e) {
    int i = blockIdx.x * blockDim.x + threadIdx.x;
    if (i < e) atomicAdd(&g_cnt[dst[i]], 1);
}

__global__ void k_scan1(int n) {                    // per-block exclusive scan
    __shared__ int sh[SCAN_B];
    int tid = threadIdx.x;
    int i = blockIdx.x * SCAN_B + tid;
    int v = (i < n) ? g_cnt[i] : 0;
    sh[tid] = v;
    __syncthreads();
    for (int off = 1; off < SCAN_B; off <<= 1) {
        int t = (tid >= off) ? sh[tid - off] : 0;
        __syncthreads();
        sh[tid] += t;
        __syncthreads();
    }
    if (i < n) g_rs[i] = sh[tid] - v;               // exclusive within block
    if (tid == SCAN_B - 1) g_bsum[blockIdx.x] = sh[tid];
}

__global__ void k_scan2(int nb) {                   // scan block sums (nb <= 256)
    __shared__ int sh[256];
    int tid = threadIdx.x;
    int v = (tid < nb) ? g_bsum[tid] : 0;
    sh[tid] = v;
    __syncthreads();
    for (int off = 1; off < 256; off <<= 1) {
        int t = (tid >= off) ? sh[tid - off] : 0;
        __syncthreads();
        sh[tid] += t;
        __syncthreads();
    }
    if (tid < nb) g_bsum[tid] = sh[tid] - v;        // exclusive
}

__global__ void k_scan3(int n) {
    int i = blockIdx.x * blockDim.x + threadIdx.x;
    if (i < n) {
        int r = g_rs[i] + g_bsum[i / SCAN_B];
        g_rs[i]  = r;
        g_cur[i] = r;
    }
}

__global__ void k_fill(const int* __restrict__ src, const int* __restrict__ dst,
                       const float* __restrict__ w, int e) {
    int i = blockIdx.x * blockDim.x + threadIdx.x;
    if (i < e) {
        int d = dst[i];
        int pos = atomicAdd(&g_cur[d], 1);
        g_edge[pos] = make_float2(__int_as_float(src[i]), w[i]);
    }
}

// ---------------- dinv = rsqrt(sum_w + 1) from CSR ----------------
__global__ void k_deg(int n) {
    int node = blockIdx.x * (blockDim.x >> 5) + (threadIdx.x >> 5);
    int lane = threadIdx.x & 31;
    if (node >= n) return;
    int beg = g_rs[node], end = beg + g_cnt[node];
    float s = 0.f;
    for (int e = beg + lane; e < end; e += 32) s += g_edge[e].y;
#pragma unroll
    for (int off = 16; off; off >>= 1) s += __shfl_xor_sync(0xffffffffu, s, off);
    if (lane == 0) g_dinv[node] = rsqrtf(s + 1.0f);
}

// ---------------- GEMM1: hs1h = fp16(dinv * (x @ W1)) ----------------
// 128 rows/block, 128 threads. Thread = 4 rows x 16 cols (64 accs).
// Inner loop: 80 smem bytes per 64 FMA -> FMA-bound.
#define G1_ROWS 128
#define G1_PAD  132
__global__ void __launch_bounds__(128)
k_gemm1(const float* __restrict__ x, const float* __restrict__ W1, int n) {
    extern __shared__ float sm[];
    float* Ws = sm;                          // [128*64] = 32KB
    float* xs = sm + D_IN * D_HID;           // [128*132] = 67.6KB
    const int tid  = threadIdx.x;
    const int row0 = blockIdx.x * G1_ROWS;

    // load W1 (float4)
    for (int i = tid; i < D_IN * D_HID / 4; i += 128)
        reinterpret_cast<float4*>(Ws)[i] = reinterpret_cast<const float4*>(W1)[i];
    // load x tile (float4, padded rows)
    for (int i = tid; i < G1_ROWS * (D_IN / 4); i += 128) {
        int r  = i >> 5;
        int c4 = i & 31;
        float4 v = make_float4(0.f, 0.f, 0.f, 0.f);
        if (row0 + r < n)
            v = reinterpret_cast<const float4*>(x + (size_t)(row0 + r) * D_IN)[c4];
        *reinterpret_cast<float4*>(xs + r * G1_PAD + c4 * 4) = v;
    }
    __syncthreads();

    const int n0 = tid >> 2;                 // 0..31; rows n0 + 32*r
    const int cg = (tid & 3) * 16;           // column group base
    float acc[4][16];
#pragma unroll
    for (int r = 0; r < 4; r++)
#pragma unroll
        for (int j = 0; j < 16; j++) acc[r][j] = 0.f;

    for (int k = 0; k < D_IN; k++) {
        float a0 = xs[(n0      ) * G1_PAD + k];
        float a1 = xs[(n0 +  32) * G1_PAD + k];
        float a2 = xs[(n0 +  64) * G1_PAD + k];
        float a3 = xs[(n0 +  96) * G1_PAD + k];
        const float4* wr = reinterpret_cast<const float4*>(Ws + k * D_HID + cg);
#pragma unroll
        for (int j4 = 0; j4 < 4; j4++) {
            float4 wv = wr[j4];
            acc[0][j4*4+0] += a0 * wv.x; acc[0][j4*4+1] += a0 * wv.y;
            acc[0][j4*4+2] += a0 * wv.z; acc[0][j4*4+3] += a0 * wv.w;
            acc[1][j4*4+0] += a1 * wv.x; acc[1][j4*4+1] += a1 * wv.y;
            acc[1][j4*4+2] += a1 * wv.z; acc[1][j4*4+3] += a1 * wv.w;
            acc[2][j4*4+0] += a2 * wv.x; acc[2][j4*4+1] += a2 * wv.y;
            acc[2][j4*4+2] += a2 * wv.z; acc[2][j4*4+3] += a2 * wv.w;
            acc[3][j4*4+0] += a3 * wv.x; acc[3][j4*4+1] += a3 * wv.y;
            acc[3][j4*4+2] += a3 * wv.z; acc[3][j4*4+3] += a3 * wv.w;
        }
    }

#pragma unroll
    for (int r = 0; r < 4; r++) {
        int row = row0 + n0 + 32 * r;
        if (row < n) {
            float di = g_dinv[row];
            __half2 hv[8];
#pragma unroll
            for (int j = 0; j < 8; j++)
                hv[j] = __floats2half2_rn(di * acc[r][2*j], di * acc[r][2*j+1]);
            __half2* dst = g_hs1h + (size_t)row * 32 + (cg >> 1);
            reinterpret_cast<uint4*>(dst)[0] = reinterpret_cast<uint4*>(hv)[0];
            reinterpret_cast<uint4*>(dst)[1] = reinterpret_cast<uint4*>(hv)[1];
        }
    }
}

// ---------------- Layer-1 gather + mid (lrelu + @W2) fused ----------------
// warp per node; lane owns cols 2*lane, 2*lane+1 (one half2).
__global__ void k_gather1_mid(const float* __restrict__ b1,
                              const float* __restrict__ W2, int n) {
    int node = blockIdx.x * (blockDim.x >> 5) + (threadIdx.x >> 5);
    int lane = threadIdx.x & 31;
    if (node >= n) return;
    int beg = g_rs[node], end = beg + g_cnt[node];
    float di = g_dinv[node];

    float2 acc = __half22float2(g_hs1h[(size_t)node * 32 + lane]);  // self-loop

    int e = beg;
    for (; e + 4 <= end; e += 4) {                 // unroll 4 for MLP
        float2 e0 = g_edge[e], e1 = g_edge[e+1], e2 = g_edge[e+2], e3 = g_edge[e+3];
        float2 h0 = __half22float2(g_hs1h[(size_t)__float_as_int(e0.x) * 32 + lane]);
        float2 h1 = __half22float2(g_hs1h[(size_t)__float_as_int(e1.x) * 32 + lane]);
        float2 h2 = __half22float2(g_hs1h[(size_t)__float_as_int(e2.x) * 32 + lane]);
        float2 h3 = __half22float2(g_hs1h[(size_t)__float_as_int(e3.x) * 32 + lane]);
        acc.x += e0.y * h0.x; acc.y += e0.y * h0.y;
        acc.x += e1.y * h1.x; acc.y += e1.y * h1.y;
        acc.x += e2.y * h2.x; acc.y += e2.y * h2.y;
        acc.x += e3.y * h3.x; acc.y += e3.y * h3.y;
    }
    for (; e < end; e++) {
        float2 ew = g_edge[e];
        float2 hv = __half22float2(g_hs1h[(size_t)__float_as_int(ew.x) * 32 + lane]);
        acc.x += ew.y * hv.x; acc.y += ew.y * hv.y;
    }

    float2 bb = __ldg(reinterpret_cast<const float2*>(b1) + lane);
    float v0 = di * acc.x + bb.x;
    float v1 = di * acc.y + bb.y;
    v0 = (v0 > 0.f) ? v0 : 0.01f * v0;
    v1 = (v1 > 0.f) ? v1 : 0.01f * v1;

    float4 wa = __ldg(reinterpret_cast<const float4*>(W2) + 2 * lane);
    float4 wb = __ldg(reinterpret_cast<const float4*>(W2) + 2 * lane + 1);
    float c0 = v0 * wa.x + v1 * wb.x;
    float c1 = v0 * wa.y + v1 * wb.y;
    float c2 = v0 * wa.z + v1 * wb.z;
    float c3 = v0 * wa.w + v1 * wb.w;
#pragma unroll
    for (int off = 16; off; off >>= 1) {
        c0 += __shfl_xor_sync(0xffffffffu, c0, off);
        c1 += __shfl_xor_sync(0xffffffffu, c1, off);
        c2 += __shfl_xor_sync(0xffffffffu, c2, off);
        c3 += __shfl_xor_sync(0xffffffffu, c3, off);
    }
    if (lane == 0)
        reinterpret_cast<float4*>(g_hs2)[node] =
            make_float4(di * c0, di * c1, di * c2, di * c3);
}

// ---------------- Layer-2 gather + softmax fused ----------------
// warp per node; lanes stride the edge list, 4-float payloads.
__global__ void k_gather2_softmax(const float* __restrict__ b2,
                                  float* __restrict__ out, int n) {
    int node = blockIdx.x * (blockDim.x >> 5) + (threadIdx.x >> 5);
    int lane = threadIdx.x & 31;
    if (node >= n) return;
    int beg = g_rs[node], end = beg + g_cnt[node];

    float a0 = 0.f, a1 = 0.f, a2 = 0.f, a3 = 0.f;
    for (int e = beg + lane; e < end; e += 32) {
        float2 ew = g_edge[e];
        float4 v = reinterpret_cast<const float4*>(g_hs2)[__float_as_int(ew.x)];
        a0 += ew.y * v.x; a1 += ew.y * v.y; a2 += ew.y * v.z; a3 += ew.y * v.w;
    }
#pragma unroll
    for (int off = 16; off; off >>= 1) {
        a0 += __shfl_xor_sync(0xffffffffu, a0, off);
        a1 += __shfl_xor_sync(0xffffffffu, a1, off);
        a2 += __shfl_xor_sync(0xffffffffu, a2, off);
        a3 += __shfl_xor_sync(0xffffffffu, a3, off);
    }
    if (lane == 0) {
        float di = g_dinv[node];
        float4 self = reinterpret_cast<const float4*>(g_hs2)[node];
        float z0 = di * (a0 + self.x) + __ldg(&b2[0]);
        float z1 = di * (a1 + self.y) + __ldg(&b2[1]);
        float z2 = di * (a2 + self.z) + __ldg(&b2[2]);
        float z3 = di * (a3 + self.w) + __ldg(&b2[3]);
        float m = fmaxf(fmaxf(z0, z1), fmaxf(z2, z3));
        float e0 = __expf(z0 - m), e1 = __expf(z1 - m);
        float e2 = __expf(z2 - m), e3 = __expf(z3 - m);
        float inv = 1.0f / (e0 + e1 + e2 + e3);
        reinterpret_cast<float4*>(out)[node] =
            make_float4(e0 * inv, e1 * inv, e2 * inv, e3 * inv);
    }
}

// ---------------- launch ----------------
extern "C" void kernel_launch(void* const* d_in, const int* in_sizes, int n_in,
                              void* d_out, int out_size) {
    const float* x   = (const float*)d_in[0];   // [N,128]
    const int*   ei  = (const int*)  d_in[1];   // [2,E]
    const float* w   = (const float*)d_in[2];   // [E]
    const float* W1  = (const float*)d_in[3];   // [128,64]
    const float* b1  = (const float*)d_in[4];   // [64]
    const float* W2  = (const float*)d_in[5];   // [64,4]
    const float* b2  = (const float*)d_in[6];   // [4]
    float* out = (float*)d_out;

    const int N = in_sizes[0] / D_IN;
    const int E = in_sizes[2];
    const int* src = ei;
    const int* dst = ei + E;
    const int NB = (N + SCAN_B - 1) / SCAN_B;

    static bool attr_set = false;
    const int g1_smem = (D_IN * D_HID + G1_ROWS * G1_PAD) * (int)sizeof(float);
    if (!attr_set) {
        cudaFuncSetAttribute(k_gemm1, cudaFuncAttributeMaxDynamicSharedMemorySize,
                             g1_smem);
        attr_set = true;
    }

    // CSR build
    k_zero  <<<(N + 255) / 256, 256>>>(N);
    k_count <<<(E + 255) / 256, 256>>>(dst, E);
    k_scan1 <<<NB, SCAN_B>>>(N);
    k_scan2 <<<1, 256>>>(NB);
    k_scan3 <<<(N + 255) / 256, 256>>>(N);
    k_fill  <<<(E + 255) / 256, 256>>>(src, dst, w, E);

    // normalization
    k_deg   <<<(N * 32 + 255) / 256, 256>>>(N);

    // layer 1
    k_gemm1 <<<(N + G1_ROWS - 1) / G1_ROWS, 128, g1_smem>>>(x, W1, N);
    k_gather1_mid <<<(N * 32 + 255) / 256, 256>>>(b1, W2, N);

    // layer 2 + softmax
    k_gather2_softmax <<<(N * 32 + 255) / 256, 256>>>(b2, out, N);
}